// round 8
// baseline (speedup 1.0000x reference)
#include <cuda_runtime.h>
#include <cuda_bf16.h>
#include <math.h>

#define B 4
#define T 1024
#define D 512
#define U 32
#define WIDTH 64
#define EPS 1e-7f
#define TT 8                  // t-tile per block in attn kernel
#define JW 71                 // window rows per tile: TT + WIDTH - 1
#define JWP 72                // padded (multiple-of-4 loop + zero tail row)

#define QK_ROWS 32            // rows per qk block
#define QK_DP   128           // d-slice per qk block (4 parts)

// Partial projections: [part][row][16 float4]: slots 0..7 = q, 8..15 = k
__device__ __align__(16) float g_part[4 * B * T * 64];

typedef unsigned long long ull;

__device__ __forceinline__ void fma2(ull& acc, ull a, ull b) {
    asm("fma.rn.f32x2 %0, %1, %2, %0;" : "+l"(acc) : "l"(a), "l"(b));
}

// Padé 7/7 tanh, clamped. Max abs err ~1.1e-4, 1 MUFU.
__device__ __forceinline__ float tanh_fast(float x) {
    x = fminf(fmaxf(x, -5.0f), 5.0f);
    const float x2 = x * x;
    const float num = fmaf(fmaf(x2 + 378.0f, x2, 17325.0f), x2, 135135.0f);
    const float den = fmaf(fmaf(fmaf(28.0f, x2, 3150.0f), x2, 62370.0f), x2, 135135.0f);
    return __fdividef(x * num, den);
}

// ---------------------------------------------------------------------------
// Kernel A: partial projections, fully smem-resident mainloop.
// grid = 128 rowblocks x 4 d-parts; 256 threads; 64 KB dynamic smem.
// thread: g = tid&7 (8 u = W slots 2g,2g+1), r = tid>>3 (row 0..31).
// mainloop per d: 1 LDS.64 (x dup, broadcast) + 2 LDS.128 (W) + 4 FFMA2.
// ---------------------------------------------------------------------------
extern __shared__ __align__(16) char qk_smem[];

__global__ __launch_bounds__(256, 3) void qk_kernel(
    const float4* __restrict__ x4,
    const float4* __restrict__ Wt4,
    const float4* __restrict__ Wx4,
    float4* __restrict__ gpart4) {
    float2* xs2 = reinterpret_cast<float2*>(qk_smem);         // [32][128] dup
    float4* Ws4 = reinterpret_cast<float4*>(qk_smem + 32768); // [128][16]

    const int tid  = threadIdx.x;
    const int rb   = blockIdx.x >> 2;
    const int p    = blockIdx.x & 3;
    const int row0 = rb * QK_ROWS;
    const int NR   = B * T;

    // stage W slice: 128 d-rows x 16 slots (slot<8 -> Wt, else Wx)
    for (int i = tid; i < QK_DP * 16; i += 256) {
        const int d = i >> 4, s = i & 15;
        Ws4[d * 16 + s] = (s < 8)
            ? Wt4[(size_t)(p * QK_DP + d) * 8 + s]
            : Wx4[(size_t)(p * QK_DP + d) * 8 + (s - 8)];
    }
    // stage x slice duplicated {v,v}: 32 rows x 32 float4
    for (int i = tid; i < QK_ROWS * 32; i += 256) {
        const int r = i >> 5, c = i & 31;
        float4 v = x4[(size_t)(row0 + r) * 128 + p * 32 + c];
        float2* dst = &xs2[r * 128 + c * 4];
        dst[0] = make_float2(v.x, v.x);
        dst[1] = make_float2(v.y, v.y);
        dst[2] = make_float2(v.z, v.z);
        dst[3] = make_float2(v.w, v.w);
    }
    __syncthreads();

    const int g = tid & 7;
    const int r = tid >> 3;

    const float2* xr = &xs2[r * 128];
    const ulonglong2* wp = reinterpret_cast<const ulonglong2*>(Ws4) + g * 2;

    ull a0 = 0, a1 = 0, a2 = 0, a3 = 0;
    #pragma unroll 8
    for (int d = 0; d < QK_DP; d++) {
        ull xv = *reinterpret_cast<const ull*>(&xr[d]);
        ulonglong2 w0 = wp[d * 16];
        ulonglong2 w1 = wp[d * 16 + 1];
        fma2(a0, xv, w0.x); fma2(a1, xv, w0.y);
        fma2(a2, xv, w1.x); fma2(a3, xv, w1.y);
    }

    const int row = row0 + r;
    const float2 f0 = *reinterpret_cast<float2*>(&a0);
    const float2 f1 = *reinterpret_cast<float2*>(&a1);
    const float2 f2 = *reinterpret_cast<float2*>(&a2);
    const float2 f3 = *reinterpret_cast<float2*>(&a3);
    float4* outp = gpart4 + ((size_t)p * NR + row) * 16 + g * 2;
    outp[0] = make_float4(f0.x, f0.y, f1.x, f1.y);
    outp[1] = make_float4(f2.x, f2.y, f3.x, f3.y);
}

// ---------------------------------------------------------------------------
// Kernel B: banded attention. TT=8, 256 threads, grid 512.
// q/k staging sums the 4 qk partials (bh folded into q here).
// Phase-2 x ring buffer prefetched at kernel entry.
// ---------------------------------------------------------------------------
__global__ __launch_bounds__(256, 3) void attn_kernel(
    const float4* __restrict__ x4,
    const float4* __restrict__ gpart4,
    const float4* __restrict__ bh4,
    const float*  __restrict__ Wa,
    const float*  __restrict__ ba,
    float4* __restrict__ out4) {
    __shared__ __align__(16) char ubuf[(TT * 36 + JW * 36) * 4];  // 11376 B
    __shared__ float  es[JW * 9];
    __shared__ float4 was4[8];
    __shared__ float  inv_s[TT];
    __shared__ float  ba_s;

    float*  qs  = reinterpret_cast<float*>(ubuf);   // [TT][36]
    float*  ks  = qs + TT * 36;                     // [JW][36]
    float2* e2s = reinterpret_cast<float2*>(ubuf);  // [JWP][8]

    const int tid   = threadIdx.x;
    const int blk   = blockIdx.x;
    const int b     = blk >> 7;            // 128 tiles per batch
    const int t0    = (blk & 127) * TT;
    const int jbase = t0 - WIDTH / 2;
    const int NR    = B * T;

    // ---- phase-2 geometry + early x prefetch (hides LDG latency) ----
    const int dg  = tid & 127;
    const int h   = tid >> 7;              // 0..1
    const int ttb = h * 4;
    const int lo  = max(ttb, -jbase);
    const int hi  = min(ttb + 3 + (WIDTH - 1), (T - 1) - jbase);
    const int n   = hi - lo + 1;
    const int n4  = (n + 3) & ~3;

    const size_t xbase = (size_t)b * T;
    const float4* xp = x4 + (xbase + jbase + lo) * 128 + dg;

    float4 buf[4];
    #pragma unroll
    for (int pf = 0; pf < 4; pf++)
        buf[pf] = (pf < n) ? xp[(size_t)pf * 128] : make_float4(0.f, 0.f, 0.f, 0.f);

    // ---- staging ----
    if (tid < 8)  was4[tid] = ((const float4*)Wa)[tid];
    if (tid == 0) ba_s = ba[0];

    // q = sum of partials + bh
    for (int i = tid; i < TT * 8; i += 256) {
        const int tt = i >> 3, w = i & 7;
        const size_t row = (size_t)(b * T + t0 + tt);
        float4 s0 = gpart4[(0 * NR + row) * 16 + w];
        float4 s1 = gpart4[(1 * NR + row) * 16 + w];
        float4 s2 = gpart4[(2 * NR + row) * 16 + w];
        float4 s3 = gpart4[(3 * NR + row) * 16 + w];
        float4 bb = bh4[w];
        ((float4*)&qs[tt * 36])[w] = make_float4(
            s0.x + s1.x + s2.x + s3.x + bb.x,
            s0.y + s1.y + s2.y + s3.y + bb.y,
            s0.z + s1.z + s2.z + s3.z + bb.z,
            s0.w + s1.w + s2.w + s3.w + bb.w);
    }
    // k = sum of partials (slots 8..15)
    for (int i = tid; i < JW * 8; i += 256) {
        const int jj = i >> 3, w = i & 7;
        const int j = jbase + jj;
        float4 o = make_float4(0.f, 0.f, 0.f, 0.f);
        if (j >= 0 && j < T) {
            const size_t row = (size_t)(b * T + j);
            float4 s0 = gpart4[(0 * NR + row) * 16 + 8 + w];
            float4 s1 = gpart4[(1 * NR + row) * 16 + 8 + w];
            float4 s2 = gpart4[(2 * NR + row) * 16 + 8 + w];
            float4 s3 = gpart4[(3 * NR + row) * 16 + 8 + w];
            o = make_float4(s0.x + s1.x + s2.x + s3.x,
                            s0.y + s1.y + s2.y + s3.y,
                            s0.z + s1.z + s2.z + s3.z,
                            s0.w + s1.w + s2.w + s3.w);
        }
        ((float4*)&ks[jj * 36])[w] = o;
    }
    __syncthreads();

    // phase 1: scores. valid iff j in range and tt <= jj <= tt+63
    for (int idx = tid; idx < JW * TT; idx += 256) {
        const int jj = idx >> 3, tt = idx & 7;
        const int j = jbase + jj;
        float ev = 0.0f;
        if (j >= 0 && j < T && jj >= tt && jj <= tt + (WIDTH - 1)) {
            const float4* qp = (const float4*)&qs[tt * 36];
            const float4* kp = (const float4*)&ks[jj * 36];
            float s = 0.0f;
            #pragma unroll
            for (int gi = 0; gi < 8; gi++) {
                float4 q4 = qp[gi], k4 = kp[gi], w4 = was4[gi];
                s = fmaf(tanh_fast(q4.x + k4.x), w4.x, s);
                s = fmaf(tanh_fast(q4.y + k4.y), w4.y, s);
                s = fmaf(tanh_fast(q4.z + k4.z), w4.z, s);
                s = fmaf(tanh_fast(q4.w + k4.w), w4.w, s);
            }
            ev = __expf(s + ba_s);
        }
        es[jj * 9 + tt] = ev;
    }
    __syncthreads();

    // row sums: warp w handles tt=w
    {
        const int w = tid >> 5, lane = tid & 31;
        float s = 0.0f;
        for (int jj = lane; jj < JW; jj += 32) s += es[jj * 9 + w];
        #pragma unroll
        for (int off = 16; off > 0; off >>= 1)
            s += __shfl_down_sync(0xffffffffu, s, off);
        if (lane == 0) inv_s[w] = __fdividef(1.0f, s + EPS);
    }
    __syncthreads();

    // normalized duplicated weights; zero tail row [JW, JWP)
    for (int idx = tid; idx < JWP * TT; idx += 256) {
        const int jj = idx >> 3, tt = idx & 7;
        const float v = (jj < JW) ? es[jj * 9 + tt] * inv_s[tt] : 0.0f;
        e2s[jj * 8 + tt] = make_float2(v, v);
    }
    __syncthreads();

    // phase 2: v[tt][d] = sum_jj e[tt][jj] * x[jbase+jj][d], MLP=4 ring
    ull acc[4][2];
    #pragma unroll
    for (int k = 0; k < 4; k++) { acc[k][0] = 0ULL; acc[k][1] = 0ULL; }

    const float2* ep = e2s + lo * 8 + ttb;

    #pragma unroll 4
    for (int jj = 0; jj < n4; jj++) {
        float4 xv = buf[jj & 3];
        if (jj + 4 < n) buf[jj & 3] = xp[(size_t)(jj + 4) * 128];
        ulonglong2 xpk = *reinterpret_cast<ulonglong2*>(&xv);
        ulonglong2 e01 = *reinterpret_cast<const ulonglong2*>(ep + (size_t)jj * 8);
        ulonglong2 e23 = *reinterpret_cast<const ulonglong2*>(ep + (size_t)jj * 8 + 2);
        fma2(acc[0][0], e01.x, xpk.x); fma2(acc[0][1], e01.x, xpk.y);
        fma2(acc[1][0], e01.y, xpk.x); fma2(acc[1][1], e01.y, xpk.y);
        fma2(acc[2][0], e23.x, xpk.x); fma2(acc[2][1], e23.x, xpk.y);
        fma2(acc[3][0], e23.y, xpk.x); fma2(acc[3][1], e23.y, xpk.y);
    }

    #pragma unroll
    for (int k = 0; k < 4; k++) {
        const float2 lo2 = *reinterpret_cast<float2*>(&acc[k][0]);
        const float2 hi2 = *reinterpret_cast<float2*>(&acc[k][1]);
        out4[(xbase + t0 + ttb + k) * 128 + dg] =
            make_float4(lo2.x, lo2.y, hi2.x, hi2.y);
    }
}

extern "C" void kernel_launch(void* const* d_in, const int* in_sizes, int n_in,
                              void* d_out, int out_size) {
    const float* x  = (const float*)d_in[0];
    const float* Wt = (const float*)d_in[1];
    const float* Wx = (const float*)d_in[2];
    const float* bh = (const float*)d_in[3];
    const float* Wa = (const float*)d_in[4];
    const float* ba = (const float*)d_in[5];
    float* out = (float*)d_out;

    float* gp;
    cudaGetSymbolAddress((void**)&gp, g_part);

    const int qk_smem_bytes = 65536;   // 32 KB x-dup + 32 KB W-slice
    cudaFuncSetAttribute(qk_kernel,
                         cudaFuncAttributeMaxDynamicSharedMemorySize,
                         qk_smem_bytes);

    qk_kernel<<<(B * T / QK_ROWS) * 4, 256, qk_smem_bytes>>>(
        (const float4*)x, (const float4*)Wt, (const float4*)Wx, (float4*)gp);
    attn_kernel<<<(B * T) / TT, 256>>>((const float4*)x, (const float4*)gp,
                                       (const float4*)bh, Wa, ba, (float4*)out);
}

// round 9
// speedup vs baseline: 1.2504x; 1.2504x over previous
#include <cuda_runtime.h>
#include <cuda_bf16.h>
#include <math.h>

#define B 4
#define T 1024
#define D 512
#define U 32
#define WIDTH 64
#define EPS 1e-7f
#define TT 8                  // t-tile per block in gather kernel
#define JW 71                 // window rows per tile: TT + WIDTH - 1
#define JWP 72                // padded (multiple-of-4 loop + zero tail row)

// Scratch: q (bh folded) / k projections [B*T][U], normalized weights [B*T][64]
__device__ __align__(16) float g_q[B * T * U];
__device__ __align__(16) float g_k[B * T * U];
__device__ __align__(16) float g_a[B * T * WIDTH];

typedef unsigned long long ull;

__device__ __forceinline__ void fma2(ull& acc, ull a, ull b) {
    asm("fma.rn.f32x2 %0, %1, %2, %0;" : "+l"(acc) : "l"(a), "l"(b));
}
__device__ __forceinline__ ull add2(ull a, ull b) {
    ull r; asm("add.rn.f32x2 %0, %1, %2;" : "=l"(r) : "l"(a), "l"(b)); return r;
}
__device__ __forceinline__ ull dup2(float v) {
    ull r; asm("mov.b64 %0, {%1, %1};" : "=l"(r) : "f"(v)); return r;
}

// Padé 7/7 tanh, clamped. Max abs err ~1.1e-4, 1 MUFU.
__device__ __forceinline__ float tanh_fast(float x) {
    x = fminf(fmaxf(x, -5.0f), 5.0f);
    const float x2 = x * x;
    const float num = fmaf(fmaf(x2 + 378.0f, x2, 17325.0f), x2, 135135.0f);
    const float den = fmaf(fmaf(fmaf(28.0f, x2, 3150.0f), x2, 62370.0f), x2, 135135.0f);
    return __fdividef(x * num, den);
}

// ---------------------------------------------------------------------------
// Kernel A (R4-proven streamer): q = x@Wt + bh ; k = x@Wx.
// 16 rows/block, 512 threads, grid 256, 4-way split-K over d.
// ---------------------------------------------------------------------------
__global__ __launch_bounds__(512) void qk_kernel(
    const float4* __restrict__ x4,
    const ulonglong2* __restrict__ Wt2,
    const ulonglong2* __restrict__ Wx2,
    const float4* __restrict__ bh4,
    float4* __restrict__ gq4,
    float4* __restrict__ gk4) {
    __shared__ float xs[16 * 516];
    __shared__ ulonglong2 red[3 * 128][2];

    const int tid  = threadIdx.x;
    const int row0 = blockIdx.x * 16;

    for (int i = tid; i < 16 * 128; i += 512) {
        const int r = i >> 7, c = i & 127;
        float4 v = x4[(size_t)(row0 + r) * 128 + c];
        float* dst = &xs[r * 516 + c * 4];
        dst[0] = v.x; dst[1] = v.y; dst[2] = v.z; dst[3] = v.w;
    }
    __syncthreads();

    const int g    = tid & 15;
    const int rg   = (tid >> 4) & 15;
    const int part = tid >> 7;

    const ulonglong2* Wb = (g < 8) ? (Wt2 + g) : (Wx2 + (g - 8));
    Wb += (size_t)part * 128 * 8;

    const float* x0 = &xs[(2 * (rg & 7)) * 516 + part * 128];
    const float* x1 = x0 + 516;

    ull a00 = 0, a01 = 0, a10 = 0, a11 = 0;
    #pragma unroll 8
    for (int d = 0; d < 128; d++) {
        ull xv0 = dup2(x0[d]);
        ull xv1 = dup2(x1[d]);
        ulonglong2 wv = Wb[d * 8];
        fma2(a00, xv0, wv.x); fma2(a01, xv0, wv.y);
        fma2(a10, xv1, wv.x); fma2(a11, xv1, wv.y);
    }

    if (part) {
        red[(part - 1) * 128 + (tid & 127)][0] = make_ulonglong2(a00, a01);
        red[(part - 1) * 128 + (tid & 127)][1] = make_ulonglong2(a10, a11);
    }
    __syncthreads();

    if (part == 0) {
        #pragma unroll
        for (int p = 0; p < 3; p++) {
            ulonglong2 r0 = red[p * 128 + tid][0];
            ulonglong2 r1 = red[p * 128 + tid][1];
            a00 = add2(a00, r0.x); a01 = add2(a01, r0.y);
            a10 = add2(a10, r1.x); a11 = add2(a11, r1.y);
        }
        const float2 f00 = *reinterpret_cast<float2*>(&a00);
        const float2 f01 = *reinterpret_cast<float2*>(&a01);
        const float2 f10 = *reinterpret_cast<float2*>(&a10);
        const float2 f11 = *reinterpret_cast<float2*>(&a11);
        const int row = row0 + 2 * (rg & 7);
        if (g < 8) {
            float4 bb = bh4[g];
            gq4[(size_t)row * 8 + g] =
                make_float4(f00.x + bb.x, f00.y + bb.y, f01.x + bb.z, f01.y + bb.w);
            gq4[(size_t)(row + 1) * 8 + g] =
                make_float4(f10.x + bb.x, f10.y + bb.y, f11.x + bb.z, f11.y + bb.w);
        } else {
            gk4[(size_t)row * 8 + (g - 8)] =
                make_float4(f00.x, f00.y, f01.x, f01.y);
            gk4[(size_t)(row + 1) * 8 + (g - 8)] =
                make_float4(f10.x, f10.y, f11.x, f11.y);
        }
    }
}

// ---------------------------------------------------------------------------
// Kernel B: scores. One warp per t-row, 8 warps/block, grid 512.
// No __syncthreads. Writes normalized a[t][64] (jj index, j = t-32+jj).
// ---------------------------------------------------------------------------
__global__ __launch_bounds__(256) void score_kernel(
    const float* __restrict__ gq,
    const float* __restrict__ gk,
    const float* __restrict__ Wa,
    const float* __restrict__ ba,
    float* __restrict__ ga) {
    __shared__ float esm[8][WIDTH + 1];

    const int tid  = threadIdx.x;
    const int w    = tid >> 5;
    const int lane = tid & 31;
    const int row  = blockIdx.x * 8 + w;    // global t-row 0..4095
    const int tloc = row & (T - 1);
    const int rowb = row & ~(T - 1);        // b*T
    const int jbase = tloc - WIDTH / 2;

    const float qv  = gq[(size_t)row * U + lane];
    const float wav = Wa[lane];
    const float bav = ba[0];

    float sum = 0.0f;
    #pragma unroll 4
    for (int jj = 0; jj < WIDTH; jj++) {
        const int j = jbase + jj;
        const bool valid = ((unsigned)j < (unsigned)T);
        float kv = 0.0f;
        if (valid) kv = gk[(size_t)(rowb + j) * U + lane];
        float s = tanh_fast(qv + kv) * wav;
        #pragma unroll
        for (int off = 16; off > 0; off >>= 1)
            s += __shfl_xor_sync(0xffffffffu, s, off);
        float ev = valid ? __expf(s + bav) : 0.0f;
        sum += ev;
        if (lane == 0) esm[w][jj] = ev;
    }
    __syncwarp();

    const float inv = __fdividef(1.0f, sum + EPS);
    ga[(size_t)row * WIDTH + lane]      = esm[w][lane] * inv;
    ga[(size_t)row * WIDTH + 32 + lane] = esm[w][lane + 32] * inv;
}

// ---------------------------------------------------------------------------
// Kernel C: gather. TT=8, 256 threads, grid 512. MLP-4 ring (proven phase 2).
// ---------------------------------------------------------------------------
__global__ __launch_bounds__(256, 4) void gather_kernel(
    const float4* __restrict__ x4,
    const float*  __restrict__ ga,
    float4* __restrict__ out4) {
    __shared__ float2 e2s[JWP * TT];     // [jj][tt], duplicated {e,e}; 4608 B

    const int tid   = threadIdx.x;
    const int blk   = blockIdx.x;
    const int b     = blk >> 7;
    const int t0    = (blk & 127) * TT;
    const int jbase = t0 - WIDTH / 2;

    // phase-2 geometry + early x prefetch
    const int dg  = tid & 127;
    const int h   = tid >> 7;
    const int ttb = h * 4;
    const int lo  = max(ttb, -jbase);
    const int hi  = min(ttb + 3 + (WIDTH - 1), (T - 1) - jbase);
    const int n   = hi - lo + 1;
    const int n4  = (n + 3) & ~3;

    const size_t xbase = (size_t)b * T;
    const float4* xp = x4 + (xbase + jbase + lo) * 128 + dg;

    float4 buf[4];
    #pragma unroll
    for (int pf = 0; pf < 4; pf++)
        buf[pf] = (pf < n) ? xp[(size_t)pf * 128] : make_float4(0.f, 0.f, 0.f, 0.f);

    // stage normalized weights: e2s[jj][tt] = a[t0+tt][jj-tt] (0 outside band)
    for (int idx = tid; idx < JWP * TT; idx += 256) {
        const int jj = idx >> 3, tt = idx & 7;
        const int jt = jj - tt;
        float v = 0.0f;
        if (jt >= 0 && jt < WIDTH)
            v = ga[(size_t)(b * T + t0 + tt) * WIDTH + jt];
        e2s[jj * TT + tt] = make_float2(v, v);
    }
    __syncthreads();

    ull acc[4][2];
    #pragma unroll
    for (int k = 0; k < 4; k++) { acc[k][0] = 0ULL; acc[k][1] = 0ULL; }

    const float2* ep = e2s + lo * TT + ttb;

    #pragma unroll 4
    for (int jj = 0; jj < n4; jj++) {
        float4 xv = buf[jj & 3];
        if (jj + 4 < n) buf[jj & 3] = xp[(size_t)(jj + 4) * 128];
        ulonglong2 xpk = *reinterpret_cast<ulonglong2*>(&xv);
        ulonglong2 e01 = *reinterpret_cast<const ulonglong2*>(ep + (size_t)jj * TT);
        ulonglong2 e23 = *reinterpret_cast<const ulonglong2*>(ep + (size_t)jj * TT + 2);
        fma2(acc[0][0], e01.x, xpk.x); fma2(acc[0][1], e01.x, xpk.y);
        fma2(acc[1][0], e01.y, xpk.x); fma2(acc[1][1], e01.y, xpk.y);
        fma2(acc[2][0], e23.x, xpk.x); fma2(acc[2][1], e23.x, xpk.y);
        fma2(acc[3][0], e23.y, xpk.x); fma2(acc[3][1], e23.y, xpk.y);
    }

    #pragma unroll
    for (int k = 0; k < 4; k++) {
        const float2 lo2 = *reinterpret_cast<float2*>(&acc[k][0]);
        const float2 hi2 = *reinterpret_cast<float2*>(&acc[k][1]);
        out4[(xbase + t0 + ttb + k) * 128 + dg] =
            make_float4(lo2.x, lo2.y, hi2.x, hi2.y);
    }
}

extern "C" void kernel_launch(void* const* d_in, const int* in_sizes, int n_in,
                              void* d_out, int out_size) {
    const float* x  = (const float*)d_in[0];
    const float* Wt = (const float*)d_in[1];
    const float* Wx = (const float*)d_in[2];
    const float* bh = (const float*)d_in[3];
    const float* Wa = (const float*)d_in[4];
    const float* ba = (const float*)d_in[5];
    float* out = (float*)d_out;

    float* gq;
    float* gk;
    float* gaw;
    cudaGetSymbolAddress((void**)&gq, g_q);
    cudaGetSymbolAddress((void**)&gk, g_k);
    cudaGetSymbolAddress((void**)&gaw, g_a);

    qk_kernel<<<(B * T) / 16, 512>>>((const float4*)x,
                                     (const ulonglong2*)Wt,
                                     (const ulonglong2*)Wx,
                                     (const float4*)bh,
                                     (float4*)gq, (float4*)gk);
    score_kernel<<<(B * T) / 8, 256>>>(gq, gk, Wa, ba, gaw);
    gather_kernel<<<(B * T) / TT, 256>>>((const float4*)x, gaw, (float4*)out);
}

// round 10
// speedup vs baseline: 1.6127x; 1.2897x over previous
#include <cuda_runtime.h>
#include <cuda_bf16.h>
#include <math.h>

#define B 4
#define T 1024
#define D 512
#define U 32
#define WIDTH 64
#define EPS 1e-7f
#define TT 8                  // t-tile per block in attn kernel
#define JW 71                 // window rows per tile: TT + WIDTH - 1
#define JWP 72                // padded (multiple-of-4 loop + zero tail row)

// Scratch: q (bh folded) and k projections, [B,T,U]
__device__ __align__(16) float g_q[B * T * U];
__device__ __align__(16) float g_k[B * T * U];

typedef unsigned long long ull;

__device__ __forceinline__ void fma2(ull& acc, ull a, ull b) {
    asm("fma.rn.f32x2 %0, %1, %2, %0;" : "+l"(acc) : "l"(a), "l"(b));
}
__device__ __forceinline__ ull add2(ull a, ull b) {
    ull r; asm("add.rn.f32x2 %0, %1, %2;" : "=l"(r) : "l"(a), "l"(b)); return r;
}
__device__ __forceinline__ ull dup2(float v) {
    ull r; asm("mov.b64 %0, {%1, %1};" : "=l"(r) : "f"(v)); return r;
}

// Padé 7/7 tanh, clamped. Max abs err ~1.1e-4, 1 MUFU.
__device__ __forceinline__ float tanh_fast(float x) {
    x = fminf(fmaxf(x, -5.0f), 5.0f);
    const float x2 = x * x;
    const float num = fmaf(fmaf(x2 + 378.0f, x2, 17325.0f), x2, 135135.0f);
    const float den = fmaf(fmaf(fmaf(28.0f, x2, 3150.0f), x2, 62370.0f), x2, 135135.0f);
    return __fdividef(x * num, den);
}

// ---------------------------------------------------------------------------
// Kernel A: q = x@Wt + bh ; k = x@Wx.
// 16 rows/block, 512 threads, grid 256, 4-way split-K over d.
// W loads go through an explicit 4-deep register ring (MLP=4).
// ---------------------------------------------------------------------------
__global__ __launch_bounds__(512) void qk_kernel(
    const float4* __restrict__ x4,
    const ulonglong2* __restrict__ Wt2,
    const ulonglong2* __restrict__ Wx2,
    const float4* __restrict__ bh4,
    float4* __restrict__ gq4,
    float4* __restrict__ gk4) {
    __shared__ float xs[16 * 516];
    __shared__ ulonglong2 red[3 * 128][2];

    const int tid  = threadIdx.x;
    const int row0 = blockIdx.x * 16;

    for (int i = tid; i < 16 * 128; i += 512) {
        const int r = i >> 7, c = i & 127;
        float4 v = x4[(size_t)(row0 + r) * 128 + c];
        float* dst = &xs[r * 516 + c * 4];
        dst[0] = v.x; dst[1] = v.y; dst[2] = v.z; dst[3] = v.w;
    }
    __syncthreads();

    const int g    = tid & 15;
    const int rg   = (tid >> 4) & 15;
    const int part = tid >> 7;

    const ulonglong2* Wb = (g < 8) ? (Wt2 + g) : (Wx2 + (g - 8));
    Wb += (size_t)part * 128 * 8;

    const float* x0 = &xs[(2 * (rg & 7)) * 516 + part * 128];
    const float* x1 = x0 + 516;

    ull a00 = 0, a01 = 0, a10 = 0, a11 = 0;

    // 4-deep W ring: 4 independent LDG.128 in flight per thread
    ulonglong2 wbuf[4];
    #pragma unroll
    for (int p = 0; p < 4; p++) wbuf[p] = Wb[p * 8];

    #pragma unroll 4
    for (int d = 0; d < 128; d++) {
        ulonglong2 wv = wbuf[d & 3];
        if (d + 4 < 128) wbuf[d & 3] = Wb[(d + 4) * 8];
        ull xv0 = dup2(x0[d]);
        ull xv1 = dup2(x1[d]);
        fma2(a00, xv0, wv.x); fma2(a01, xv0, wv.y);
        fma2(a10, xv1, wv.x); fma2(a11, xv1, wv.y);
    }

    if (part) {
        red[(part - 1) * 128 + (tid & 127)][0] = make_ulonglong2(a00, a01);
        red[(part - 1) * 128 + (tid & 127)][1] = make_ulonglong2(a10, a11);
    }
    __syncthreads();

    if (part == 0) {
        #pragma unroll
        for (int p = 0; p < 3; p++) {
            ulonglong2 r0 = red[p * 128 + tid][0];
            ulonglong2 r1 = red[p * 128 + tid][1];
            a00 = add2(a00, r0.x); a01 = add2(a01, r0.y);
            a10 = add2(a10, r1.x); a11 = add2(a11, r1.y);
        }
        const float2 f00 = *reinterpret_cast<float2*>(&a00);
        const float2 f01 = *reinterpret_cast<float2*>(&a01);
        const float2 f10 = *reinterpret_cast<float2*>(&a10);
        const float2 f11 = *reinterpret_cast<float2*>(&a11);
        const int row = row0 + 2 * (rg & 7);
        if (g < 8) {
            float4 bb = bh4[g];
            gq4[(size_t)row * 8 + g] =
                make_float4(f00.x + bb.x, f00.y + bb.y, f01.x + bb.z, f01.y + bb.w);
            gq4[(size_t)(row + 1) * 8 + g] =
                make_float4(f10.x + bb.x, f10.y + bb.y, f11.x + bb.z, f11.y + bb.w);
        } else {
            gk4[(size_t)row * 8 + (g - 8)] =
                make_float4(f00.x, f00.y, f01.x, f01.y);
            gk4[(size_t)(row + 1) * 8 + (g - 8)] =
                make_float4(f10.x, f10.y, f11.x, f11.y);
        }
    }
}

// ---------------------------------------------------------------------------
// Kernel B (R7-proven): banded attention. TT=8, 256 threads, grid 512.
// ---------------------------------------------------------------------------
__global__ __launch_bounds__(256) void attn_kernel(
    const float4* __restrict__ x4,
    const float4* __restrict__ gq4,
    const float4* __restrict__ gk4,
    const float*  __restrict__ Wa,
    const float*  __restrict__ ba,
    float4* __restrict__ out4) {
    __shared__ __align__(16) char ubuf[(TT * 36 + JW * 36) * 4];
    __shared__ float  es[JW * 9];
    __shared__ float4 was4[8];
    __shared__ float  inv_s[TT];
    __shared__ float  ba_s;

    float*  qs  = reinterpret_cast<float*>(ubuf);   // [TT][36]
    float*  ks  = qs + TT * 36;                     // [JW][36]
    float2* e2s = reinterpret_cast<float2*>(ubuf);  // [JWP][8]

    const int tid   = threadIdx.x;
    const int blk   = blockIdx.x;
    const int b     = blk >> 7;
    const int t0    = (blk & 127) * TT;
    const int jbase = t0 - WIDTH / 2;

    if (tid < 8)  was4[tid] = ((const float4*)Wa)[tid];
    if (tid == 0) ba_s = ba[0];

    for (int i = tid; i < TT * 8; i += 256) {
        const int tt = i >> 3, w = i & 7;
        ((float4*)&qs[tt * 36])[w] = gq4[((size_t)(b * T + t0 + tt)) * 8 + w];
    }
    for (int i = tid; i < JW * 8; i += 256) {
        const int jj = i >> 3, w = i & 7;
        const int j = jbase + jj;
        ((float4*)&ks[jj * 36])[w] = (j >= 0 && j < T)
            ? gk4[((size_t)(b * T + j)) * 8 + w]
            : make_float4(0.f, 0.f, 0.f, 0.f);
    }
    __syncthreads();

    for (int idx = tid; idx < JW * TT; idx += 256) {
        const int jj = idx >> 3, tt = idx & 7;
        const int j = jbase + jj;
        float ev = 0.0f;
        if (j >= 0 && j < T && jj >= tt && jj <= tt + (WIDTH - 1)) {
            const float4* qp = (const float4*)&qs[tt * 36];
            const float4* kp = (const float4*)&ks[jj * 36];
            float s = 0.0f;
            #pragma unroll
            for (int gi = 0; gi < 8; gi++) {
                float4 q4 = qp[gi], k4 = kp[gi], w4 = was4[gi];
                s = fmaf(tanh_fast(q4.x + k4.x), w4.x, s);
                s = fmaf(tanh_fast(q4.y + k4.y), w4.y, s);
                s = fmaf(tanh_fast(q4.z + k4.z), w4.z, s);
                s = fmaf(tanh_fast(q4.w + k4.w), w4.w, s);
            }
            ev = __expf(s + ba_s);
        }
        es[jj * 9 + tt] = ev;
    }
    __syncthreads();

    {
        const int w = tid >> 5, lane = tid & 31;
        float s = 0.0f;
        for (int jj = lane; jj < JW; jj += 32) s += es[jj * 9 + w];
        #pragma unroll
        for (int off = 16; off > 0; off >>= 1)
            s += __shfl_down_sync(0xffffffffu, s, off);
        if (lane == 0) inv_s[w] = __fdividef(1.0f, s + EPS);
    }
    __syncthreads();

    for (int idx = tid; idx < JWP * TT; idx += 256) {
        const int jj = idx >> 3, tt = idx & 7;
        const float v = (jj < JW) ? es[jj * 9 + tt] * inv_s[tt] : 0.0f;
        e2s[jj * 8 + tt] = make_float2(v, v);
    }
    __syncthreads();

    const int dg  = tid & 127;
    const int h   = tid >> 7;
    const int ttb = h * 4;

    const int lo = max(ttb, -jbase);
    const int hi = min(ttb + 3 + (WIDTH - 1), (T - 1) - jbase);
    const int n  = hi - lo + 1;
    const int n4 = (n + 3) & ~3;

    ull acc[4][2];
    #pragma unroll
    for (int k = 0; k < 4; k++) { acc[k][0] = 0ULL; acc[k][1] = 0ULL; }

    const size_t xbase = (size_t)b * T;
    const float4* xp = x4 + (xbase + jbase + lo) * 128 + dg;
    const float2* ep = e2s + lo * 8 + ttb;

    float4 buf[4];
    #pragma unroll
    for (int p = 0; p < 4; p++)
        buf[p] = (p < n) ? xp[(size_t)p * 128] : make_float4(0.f, 0.f, 0.f, 0.f);

    #pragma unroll 4
    for (int jj = 0; jj < n4; jj++) {
        float4 xv = buf[jj & 3];
        if (jj + 4 < n) buf[jj & 3] = xp[(size_t)(jj + 4) * 128];
        ulonglong2 xpk = *reinterpret_cast<ulonglong2*>(&xv);
        ulonglong2 e01 = *reinterpret_cast<const ulonglong2*>(ep + (size_t)jj * 8);
        ulonglong2 e23 = *reinterpret_cast<const ulonglong2*>(ep + (size_t)jj * 8 + 2);
        fma2(acc[0][0], e01.x, xpk.x); fma2(acc[0][1], e01.x, xpk.y);
        fma2(acc[1][0], e01.y, xpk.x); fma2(acc[1][1], e01.y, xpk.y);
        fma2(acc[2][0], e23.x, xpk.x); fma2(acc[2][1], e23.x, xpk.y);
        fma2(acc[3][0], e23.y, xpk.x); fma2(acc[3][1], e23.y, xpk.y);
    }

    #pragma unroll
    for (int k = 0; k < 4; k++) {
        const float2 lo2 = *reinterpret_cast<float2*>(&acc[k][0]);
        const float2 hi2 = *reinterpret_cast<float2*>(&acc[k][1]);
        out4[(xbase + t0 + ttb + k) * 128 + dg] =
            make_float4(lo2.x, lo2.y, hi2.x, hi2.y);
    }
}

extern "C" void kernel_launch(void* const* d_in, const int* in_sizes, int n_in,
                              void* d_out, int out_size) {
    const float* x  = (const float*)d_in[0];
    const float* Wt = (const float*)d_in[1];
    const float* Wx = (const float*)d_in[2];
    const float* bh = (const float*)d_in[3];
    const float* Wa = (const float*)d_in[4];
    const float* ba = (const float*)d_in[5];
    float* out = (float*)d_out;

    float* gq;
    float* gk;
    cudaGetSymbolAddress((void**)&gq, g_q);
    cudaGetSymbolAddress((void**)&gk, g_k);

    qk_kernel<<<(B * T) / 16, 512>>>((const float4*)x,
                                     (const ulonglong2*)Wt,
                                     (const ulonglong2*)Wx,
                                     (const float4*)bh,
                                     (float4*)gq, (float4*)gk);
    attn_kernel<<<(B * T) / TT, 256>>>((const float4*)x,
                                       (const float4*)gq, (const float4*)gk,
                                       Wa, ba, (float4*)out);
}

// round 11
// speedup vs baseline: 1.7597x; 1.0911x over previous
#include <cuda_runtime.h>
#include <cuda_bf16.h>
#include <math.h>

#define B 4
#define T 1024
#define D 512
#define U 32
#define WIDTH 64
#define EPS 1e-7f
#define TT 8
#define JW 71
#define JWP 72

#define LOG2E 1.4426950408889634f
#define C2    2.8853900817779268f   // 2*log2(e)

// Scratch: q' = (x@Wt + bh)*C2, k' = (x@Wx)*C2, [B,T,U]
__device__ __align__(16) float g_q[B * T * U];
__device__ __align__(16) float g_k[B * T * U];

typedef unsigned long long ull;

__device__ __forceinline__ void fma2(ull& acc, ull a, ull b) {
    asm("fma.rn.f32x2 %0, %1, %2, %0;" : "+l"(acc) : "l"(a), "l"(b));
}
__device__ __forceinline__ ull add2(ull a, ull b) {
    ull r; asm("add.rn.f32x2 %0, %1, %2;" : "=l"(r) : "l"(a), "l"(b)); return r;
}
__device__ __forceinline__ ull dup2(float v) {
    ull r; asm("mov.b64 %0, {%1, %1};" : "=l"(r) : "f"(v)); return r;
}
__device__ __forceinline__ float ex2f(float z) {
    float r; asm("ex2.approx.ftz.f32 %0, %1;" : "=f"(r) : "f"(z)); return r;
}
__device__ __forceinline__ float rcpf(float z) {
    float r; asm("rcp.approx.ftz.f32 %0, %1;" : "=f"(r) : "f"(z)); return r;
}
// tanh(a) where z = a*2*log2(e):  1 - 2/(2^z + 1). 6 instr incl. caller's add.
__device__ __forceinline__ float tanh2(float z) {
    const float ex = ex2f(z);
    const float r  = rcpf(ex + 1.0f);
    return fmaf(-2.0f, r, 1.0f);
}

// ---------------------------------------------------------------------------
// Kernel A: q' = (x@Wt + bh)*C2 ; k' = (x@Wx)*C2.
// 16 rows/block, 512 threads, grid 256, 4-way split-K, 4-deep W ring.
// ---------------------------------------------------------------------------
__global__ __launch_bounds__(512) void qk_kernel(
    const float4* __restrict__ x4,
    const ulonglong2* __restrict__ Wt2,
    const ulonglong2* __restrict__ Wx2,
    const float4* __restrict__ bh4,
    float4* __restrict__ gq4,
    float4* __restrict__ gk4) {
    __shared__ float xs[16 * 516];
    __shared__ ulonglong2 red[3 * 128][2];

    const int tid  = threadIdx.x;
    const int row0 = blockIdx.x * 16;

    for (int i = tid; i < 16 * 128; i += 512) {
        const int r = i >> 7, c = i & 127;
        float4 v = x4[(size_t)(row0 + r) * 128 + c];
        float* dst = &xs[r * 516 + c * 4];
        dst[0] = v.x; dst[1] = v.y; dst[2] = v.z; dst[3] = v.w;
    }
    __syncthreads();

    const int g    = tid & 15;
    const int rg   = (tid >> 4) & 15;
    const int part = tid >> 7;

    const ulonglong2* Wb = (g < 8) ? (Wt2 + g) : (Wx2 + (g - 8));
    Wb += (size_t)part * 128 * 8;

    const float* x0 = &xs[(2 * (rg & 7)) * 516 + part * 128];
    const float* x1 = x0 + 516;

    ull a00 = 0, a01 = 0, a10 = 0, a11 = 0;

    ulonglong2 wbuf[4];
    #pragma unroll
    for (int p = 0; p < 4; p++) wbuf[p] = Wb[p * 8];

    #pragma unroll 4
    for (int d = 0; d < 128; d++) {
        ulonglong2 wv = wbuf[d & 3];
        if (d + 4 < 128) wbuf[d & 3] = Wb[(d + 4) * 8];
        ull xv0 = dup2(x0[d]);
        ull xv1 = dup2(x1[d]);
        fma2(a00, xv0, wv.x); fma2(a01, xv0, wv.y);
        fma2(a10, xv1, wv.x); fma2(a11, xv1, wv.y);
    }

    if (part) {
        red[(part - 1) * 128 + (tid & 127)][0] = make_ulonglong2(a00, a01);
        red[(part - 1) * 128 + (tid & 127)][1] = make_ulonglong2(a10, a11);
    }
    __syncthreads();

    if (part == 0) {
        #pragma unroll
        for (int p = 0; p < 3; p++) {
            ulonglong2 r0 = red[p * 128 + tid][0];
            ulonglong2 r1 = red[p * 128 + tid][1];
            a00 = add2(a00, r0.x); a01 = add2(a01, r0.y);
            a10 = add2(a10, r1.x); a11 = add2(a11, r1.y);
        }
        const float2 f00 = *reinterpret_cast<float2*>(&a00);
        const float2 f01 = *reinterpret_cast<float2*>(&a01);
        const float2 f10 = *reinterpret_cast<float2*>(&a10);
        const float2 f11 = *reinterpret_cast<float2*>(&a11);
        const int row = row0 + 2 * (rg & 7);
        if (g < 8) {
            float4 bb = bh4[g];
            gq4[(size_t)row * 8 + g] = make_float4(
                (f00.x + bb.x) * C2, (f00.y + bb.y) * C2,
                (f01.x + bb.z) * C2, (f01.y + bb.w) * C2);
            gq4[(size_t)(row + 1) * 8 + g] = make_float4(
                (f10.x + bb.x) * C2, (f10.y + bb.y) * C2,
                (f11.x + bb.z) * C2, (f11.y + bb.w) * C2);
        } else {
            gk4[(size_t)row * 8 + (g - 8)] = make_float4(
                f00.x * C2, f00.y * C2, f01.x * C2, f01.y * C2);
            gk4[(size_t)(row + 1) * 8 + (g - 8)] = make_float4(
                f10.x * C2, f10.y * C2, f11.x * C2, f11.y * C2);
        }
    }
}

// ---------------------------------------------------------------------------
// Kernel B: banded attention. TT=8, 256 threads, grid 512.
// Phase 1 uses exp2-form tanh on pre-scaled q'/k', q held in registers.
// ---------------------------------------------------------------------------
__global__ __launch_bounds__(256, 4) void attn_kernel(
    const float4* __restrict__ x4,
    const float4* __restrict__ gq4,
    const float4* __restrict__ gk4,
    const float*  __restrict__ Wa,
    const float*  __restrict__ ba,
    float4* __restrict__ out4) {
    __shared__ __align__(16) char ubuf[(TT * 36 + JW * 36) * 4];
    __shared__ float  es[JW * 9];
    __shared__ float4 was4[8];       // Wa * log2(e)
    __shared__ float  inv_s[TT];
    __shared__ float  baL_s;         // ba * log2(e)

    float*  qs  = reinterpret_cast<float*>(ubuf);   // [TT][36]
    float*  ks  = qs + TT * 36;                     // [JW][36]
    float2* e2s = reinterpret_cast<float2*>(ubuf);  // [JWP][8]

    const int tid   = threadIdx.x;
    const int blk   = blockIdx.x;
    const int b     = blk >> 7;
    const int t0    = (blk & 127) * TT;
    const int jbase = t0 - WIDTH / 2;

    if (tid < 8) {
        float4 w = ((const float4*)Wa)[tid];
        was4[tid] = make_float4(w.x * LOG2E, w.y * LOG2E,
                                w.z * LOG2E, w.w * LOG2E);
    }
    if (tid == 0) baL_s = ba[0] * LOG2E;

    for (int i = tid; i < TT * 8; i += 256) {
        const int tt = i >> 3, w = i & 7;
        ((float4*)&qs[tt * 36])[w] = gq4[((size_t)(b * T + t0 + tt)) * 8 + w];
    }
    for (int i = tid; i < JW * 8; i += 256) {
        const int jj = i >> 3, w = i & 7;
        const int j = jbase + jj;
        ((float4*)&ks[jj * 36])[w] = (j >= 0 && j < T)
            ? gk4[((size_t)(b * T + j)) * 8 + w]
            : make_float4(0.f, 0.f, 0.f, 0.f);
    }
    __syncthreads();

    // phase 1: scores. thread = (tt = tid&7, jj0 = tid>>3, step 32).
    {
        const int tt  = tid & 7;
        const int jj0 = tid >> 3;
        float4 qr[8];
        const float4* qp = (const float4*)&qs[tt * 36];
        #pragma unroll
        for (int gi = 0; gi < 8; gi++) qr[gi] = qp[gi];
        const float baL = baL_s;

        for (int jj = jj0; jj < JW; jj += 32) {
            const int j = jbase + jj;
            float ev = 0.0f;
            if (j >= 0 && j < T && jj >= tt && jj <= tt + (WIDTH - 1)) {
                const float4* kp = (const float4*)&ks[jj * 36];
                float s = baL;
                #pragma unroll
                for (int gi = 0; gi < 8; gi++) {
                    float4 k4 = kp[gi], w4 = was4[gi];
                    s = fmaf(tanh2(qr[gi].x + k4.x), w4.x, s);
                    s = fmaf(tanh2(qr[gi].y + k4.y), w4.y, s);
                    s = fmaf(tanh2(qr[gi].z + k4.z), w4.z, s);
                    s = fmaf(tanh2(qr[gi].w + k4.w), w4.w, s);
                }
                ev = ex2f(s);
            }
            es[jj * 9 + tt] = ev;
        }
    }
    __syncthreads();

    // row sums: warp w handles tt=w
    {
        const int w = tid >> 5, lane = tid & 31;
        float s = 0.0f;
        for (int jj = lane; jj < JW; jj += 32) s += es[jj * 9 + w];
        #pragma unroll
        for (int off = 16; off > 0; off >>= 1)
            s += __shfl_down_sync(0xffffffffu, s, off);
        if (lane == 0) inv_s[w] = __fdividef(1.0f, s + EPS);
    }
    __syncthreads();

    // normalized duplicated weights; zero tail row [JW, JWP)
    for (int idx = tid; idx < JWP * TT; idx += 256) {
        const int jj = idx >> 3, tt = idx & 7;
        const float v = (jj < JW) ? es[jj * 9 + tt] * inv_s[tt] : 0.0f;
        e2s[jj * 8 + tt] = make_float2(v, v);
    }
    __syncthreads();

    // phase 2: v[tt][d] = sum_jj e[tt][jj] * x[jbase+jj][d], MLP=4 ring
    const int dg  = tid & 127;
    const int h   = tid >> 7;
    const int ttb = h * 4;

    const int lo = max(ttb, -jbase);
    const int hi = min(ttb + 3 + (WIDTH - 1), (T - 1) - jbase);
    const int n  = hi - lo + 1;
    const int n4 = (n + 3) & ~3;

    ull acc[4][2];
    #pragma unroll
    for (int k = 0; k < 4; k++) { acc[k][0] = 0ULL; acc[k][1] = 0ULL; }

    const size_t xbase = (size_t)b * T;
    const float4* xp = x4 + (xbase + jbase + lo) * 128 + dg;
    const float2* ep = e2s + lo * 8 + ttb;

    float4 buf[4];
    #pragma unroll
    for (int p = 0; p < 4; p++)
        buf[p] = (p < n) ? xp[(size_t)p * 128] : make_float4(0.f, 0.f, 0.f, 0.f);

    #pragma unroll 4
    for (int jj = 0; jj < n4; jj++) {
        float4 xv = buf[jj & 3];
        if (jj + 4 < n) buf[jj & 3] = xp[(size_t)(jj + 4) * 128];
        ulonglong2 xpk = *reinterpret_cast<ulonglong2*>(&xv);
        ulonglong2 e01 = *reinterpret_cast<const ulonglong2*>(ep + (size_t)jj * 8);
        ulonglong2 e23 = *reinterpret_cast<const ulonglong2*>(ep + (size_t)jj * 8 + 2);
        fma2(acc[0][0], e01.x, xpk.x); fma2(acc[0][1], e01.x, xpk.y);
        fma2(acc[1][0], e01.y, xpk.x); fma2(acc[1][1], e01.y, xpk.y);
        fma2(acc[2][0], e23.x, xpk.x); fma2(acc[2][1], e23.x, xpk.y);
        fma2(acc[3][0], e23.y, xpk.x); fma2(acc[3][1], e23.y, xpk.y);
    }

    #pragma unroll
    for (int k = 0; k < 4; k++) {
        const float2 lo2 = *reinterpret_cast<float2*>(&acc[k][0]);
        const float2 hi2 = *reinterpret_cast<float2*>(&acc[k][1]);
        out4[(xbase + t0 + ttb + k) * 128 + dg] =
            make_float4(lo2.x, lo2.y, hi2.x, hi2.y);
    }
}

extern "C" void kernel_launch(void* const* d_in, const int* in_sizes, int n_in,
                              void* d_out, int out_size) {
    const float* x  = (const float*)d_in[0];
    const float* Wt = (const float*)d_in[1];
    const float* Wx = (const float*)d_in[2];
    const float* bh = (const float*)d_in[3];
    const float* Wa = (const float*)d_in[4];
    const float* ba = (const float*)d_in[5];
    float* out = (float*)d_out;

    float* gq;
    float* gk;
    cudaGetSymbolAddress((void**)&gq, g_q);
    cudaGetSymbolAddress((void**)&gk, g_k);

    qk_kernel<<<(B * T) / 16, 512>>>((const float4*)x,
                                     (const ulonglong2*)Wt,
                                     (const ulonglong2*)Wx,
                                     (const float4*)bh,
                                     (float4*)gq, (float4*)gk);
    attn_kernel<<<(B * T) / TT, 256>>>((const float4*)x,
                                       (const float4*)gq, (const float4*)gk,
                                       Wa, ba, (float4*)out);
}

// round 12
// speedup vs baseline: 1.7871x; 1.0156x over previous
#include <cuda_runtime.h>
#include <cuda_bf16.h>
#include <math.h>

#define B 4
#define T 1024
#define D 512
#define U 32
#define WIDTH 64
#define EPS 1e-7f
#define TT 8
#define JW 71
#define JWP 72

#define LOG2E 1.4426950408889634f
#define C2    2.8853900817779268f   // 2*log2(e)

// Scratch: q' = (x@Wt + bh)*C2, k' = (x@Wx)*C2, [B,T,U]
__device__ __align__(16) float g_q[B * T * U];
__device__ __align__(16) float g_k[B * T * U];

typedef unsigned long long ull;

__device__ __forceinline__ void fma2(ull& acc, ull a, ull b) {
    asm("fma.rn.f32x2 %0, %1, %2, %0;" : "+l"(acc) : "l"(a), "l"(b));
}
__device__ __forceinline__ ull add2(ull a, ull b) {
    ull r; asm("add.rn.f32x2 %0, %1, %2;" : "=l"(r) : "l"(a), "l"(b)); return r;
}
__device__ __forceinline__ ull dup2(float v) {
    ull r; asm("mov.b64 %0, {%1, %1};" : "=l"(r) : "f"(v)); return r;
}
__device__ __forceinline__ float ex2f(float z) {
    float r; asm("ex2.approx.ftz.f32 %0, %1;" : "=f"(r) : "f"(z)); return r;
}
__device__ __forceinline__ float rcpf(float z) {
    float r; asm("rcp.approx.ftz.f32 %0, %1;" : "=f"(r) : "f"(z)); return r;
}
// tanh(a) where z = a*2*log2(e):  1 - 2/(2^z + 1).
__device__ __forceinline__ float tanh2(float z) {
    const float ex = ex2f(z);
    const float r  = rcpf(ex + 1.0f);
    return fmaf(-2.0f, r, 1.0f);
}

// ---------------------------------------------------------------------------
// Kernel A (frozen from R11): q' = (x@Wt + bh)*C2 ; k' = (x@Wx)*C2.
// ---------------------------------------------------------------------------
__global__ __launch_bounds__(512) void qk_kernel(
    const float4* __restrict__ x4,
    const ulonglong2* __restrict__ Wt2,
    const ulonglong2* __restrict__ Wx2,
    const float4* __restrict__ bh4,
    float4* __restrict__ gq4,
    float4* __restrict__ gk4) {
    __shared__ float xs[16 * 516];
    __shared__ ulonglong2 red[3 * 128][2];

    const int tid  = threadIdx.x;
    const int row0 = blockIdx.x * 16;

    for (int i = tid; i < 16 * 128; i += 512) {
        const int r = i >> 7, c = i & 127;
        float4 v = x4[(size_t)(row0 + r) * 128 + c];
        float* dst = &xs[r * 516 + c * 4];
        dst[0] = v.x; dst[1] = v.y; dst[2] = v.z; dst[3] = v.w;
    }
    __syncthreads();

    const int g    = tid & 15;
    const int rg   = (tid >> 4) & 15;
    const int part = tid >> 7;

    const ulonglong2* Wb = (g < 8) ? (Wt2 + g) : (Wx2 + (g - 8));
    Wb += (size_t)part * 128 * 8;

    const float* x0 = &xs[(2 * (rg & 7)) * 516 + part * 128];
    const float* x1 = x0 + 516;

    ull a00 = 0, a01 = 0, a10 = 0, a11 = 0;

    ulonglong2 wbuf[4];
    #pragma unroll
    for (int p = 0; p < 4; p++) wbuf[p] = Wb[p * 8];

    #pragma unroll 4
    for (int d = 0; d < 128; d++) {
        ulonglong2 wv = wbuf[d & 3];
        if (d + 4 < 128) wbuf[d & 3] = Wb[(d + 4) * 8];
        ull xv0 = dup2(x0[d]);
        ull xv1 = dup2(x1[d]);
        fma2(a00, xv0, wv.x); fma2(a01, xv0, wv.y);
        fma2(a10, xv1, wv.x); fma2(a11, xv1, wv.y);
    }

    if (part) {
        red[(part - 1) * 128 + (tid & 127)][0] = make_ulonglong2(a00, a01);
        red[(part - 1) * 128 + (tid & 127)][1] = make_ulonglong2(a10, a11);
    }
    __syncthreads();

    if (part == 0) {
        #pragma unroll
        for (int p = 0; p < 3; p++) {
            ulonglong2 r0 = red[p * 128 + tid][0];
            ulonglong2 r1 = red[p * 128 + tid][1];
            a00 = add2(a00, r0.x); a01 = add2(a01, r0.y);
            a10 = add2(a10, r1.x); a11 = add2(a11, r1.y);
        }
        const float2 f00 = *reinterpret_cast<float2*>(&a00);
        const float2 f01 = *reinterpret_cast<float2*>(&a01);
        const float2 f10 = *reinterpret_cast<float2*>(&a10);
        const float2 f11 = *reinterpret_cast<float2*>(&a11);
        const int row = row0 + 2 * (rg & 7);
        if (g < 8) {
            float4 bb = bh4[g];
            gq4[(size_t)row * 8 + g] = make_float4(
                (f00.x + bb.x) * C2, (f00.y + bb.y) * C2,
                (f01.x + bb.z) * C2, (f01.y + bb.w) * C2);
            gq4[(size_t)(row + 1) * 8 + g] = make_float4(
                (f10.x + bb.x) * C2, (f10.y + bb.y) * C2,
                (f11.x + bb.z) * C2, (f11.y + bb.w) * C2);
        } else {
            gk4[(size_t)row * 8 + (g - 8)] = make_float4(
                f00.x * C2, f00.y * C2, f01.x * C2, f01.y * C2);
            gk4[(size_t)(row + 1) * 8 + (g - 8)] = make_float4(
                f10.x * C2, f10.y * C2, f11.x * C2, f11.y * C2);
        }
    }
}

// ---------------------------------------------------------------------------
// Kernel B: banded attention, 2-barrier structure.
// stage -> bar -> score(+inline row-sum partials) -> bar -> gather -> scale.
// ---------------------------------------------------------------------------
__global__ __launch_bounds__(256, 4) void attn_kernel(
    const float4* __restrict__ x4,
    const float4* __restrict__ gq4,
    const float4* __restrict__ gk4,
    const float*  __restrict__ Wa,
    const float*  __restrict__ ba,
    float4* __restrict__ out4) {
    __shared__ float  qs[TT * 36];       // 1152 B
    __shared__ float  ks[JW * 36];       // 10224 B
    __shared__ float2 e2s[JWP * TT];     // 4608 B, unnormalized dup weights
    __shared__ float  wsum[8][8];        // per-warp partial row sums
    __shared__ float4 was4[8];           // Wa * log2(e)
    __shared__ float  baL_s;             // ba * log2(e)

    const int tid   = threadIdx.x;
    const int blk   = blockIdx.x;
    const int b     = blk >> 7;
    const int t0    = (blk & 127) * TT;
    const int jbase = t0 - WIDTH / 2;

    if (tid < 8) {
        float4 w = ((const float4*)Wa)[tid];
        was4[tid] = make_float4(w.x * LOG2E, w.y * LOG2E,
                                w.z * LOG2E, w.w * LOG2E);
    }
    if (tid == 0) baL_s = ba[0] * LOG2E;

    for (int i = tid; i < TT * 8; i += 256) {
        const int tt = i >> 3, w = i & 7;
        ((float4*)&qs[tt * 36])[w] = gq4[((size_t)(b * T + t0 + tt)) * 8 + w];
    }
    for (int i = tid; i < JW * 8; i += 256) {
        const int jj = i >> 3, w = i & 7;
        const int j = jbase + jj;
        ((float4*)&ks[jj * 36])[w] = (j >= 0 && j < T)
            ? gk4[((size_t)(b * T + j)) * 8 + w]
            : make_float4(0.f, 0.f, 0.f, 0.f);
    }
    __syncthreads();

    // ---- score phase: thread (tt = tid&7, jj = tid>>3 stepping 32) ----
    {
        const int tt  = tid & 7;
        const int jj0 = tid >> 3;
        float4 qr[8];
        const float4* qp = (const float4*)&qs[tt * 36];
        #pragma unroll
        for (int gi = 0; gi < 8; gi++) qr[gi] = qp[gi];
        const float baL = baL_s;

        float ps = 0.0f;   // partial row sum for this tt
        for (int jj = jj0; jj < JWP; jj += 32) {
            const int j = jbase + jj;
            float ev = 0.0f;
            if ((unsigned)j < (unsigned)T &&
                (unsigned)(jj - tt) < (unsigned)WIDTH) {
                const float4* kp = (const float4*)&ks[jj * 36];
                float s = baL;
                #pragma unroll
                for (int gi = 0; gi < 8; gi++) {
                    float4 k4 = kp[gi], w4 = was4[gi];
                    s = fmaf(tanh2(qr[gi].x + k4.x), w4.x, s);
                    s = fmaf(tanh2(qr[gi].y + k4.y), w4.y, s);
                    s = fmaf(tanh2(qr[gi].z + k4.z), w4.z, s);
                    s = fmaf(tanh2(qr[gi].w + k4.w), w4.w, s);
                }
                ev = ex2f(s);
            }
            e2s[jj * TT + tt] = make_float2(ev, ev);
            ps += ev;
        }
        // reduce over lanes with the same tt (lane, lane^8, lane^16, lane^24)
        ps += __shfl_xor_sync(0xffffffffu, ps, 8);
        ps += __shfl_xor_sync(0xffffffffu, ps, 16);
        const int w = tid >> 5, lane = tid & 31;
        if (lane < 8) wsum[w][lane] = ps;
    }
    __syncthreads();

    // ---- gather phase: unnormalized accumulation, MLP=4 ring ----
    const int dg  = tid & 127;
    const int h   = tid >> 7;
    const int ttb = h * 4;

    const int lo = max(ttb, -jbase);
    const int hi = min(ttb + 3 + (WIDTH - 1), (T - 1) - jbase);
    const int n  = hi - lo + 1;
    const int n4 = (n + 3) & ~3;

    ull acc[4][2];
    #pragma unroll
    for (int k = 0; k < 4; k++) { acc[k][0] = 0ULL; acc[k][1] = 0ULL; }

    const size_t xbase = (size_t)b * T;
    const float4* xp = x4 + (xbase + jbase + lo) * 128 + dg;
    const float2* ep = e2s + lo * TT + ttb;

    float4 buf[4];
    #pragma unroll
    for (int p = 0; p < 4; p++)
        buf[p] = (p < n) ? xp[(size_t)p * 128] : make_float4(0.f, 0.f, 0.f, 0.f);

    #pragma unroll 4
    for (int jj = 0; jj < n4; jj++) {
        float4 xv = buf[jj & 3];
        if (jj + 4 < n) buf[jj & 3] = xp[(size_t)(jj + 4) * 128];
        ulonglong2 xpk = *reinterpret_cast<ulonglong2*>(&xv);
        ulonglong2 e01 = *reinterpret_cast<const ulonglong2*>(ep + (size_t)jj * TT);
        ulonglong2 e23 = *reinterpret_cast<const ulonglong2*>(ep + (size_t)jj * TT + 2);
        fma2(acc[0][0], e01.x, xpk.x); fma2(acc[0][1], e01.x, xpk.y);
        fma2(acc[1][0], e01.y, xpk.x); fma2(acc[1][1], e01.y, xpk.y);
        fma2(acc[2][0], e23.x, xpk.x); fma2(acc[2][1], e23.x, xpk.y);
        fma2(acc[3][0], e23.y, xpk.x); fma2(acc[3][1], e23.y, xpk.y);
    }

    // ---- epilogue: normalize and store ----
    #pragma unroll
    for (int k = 0; k < 4; k++) {
        float s = 0.0f;
        #pragma unroll
        for (int w = 0; w < 8; w++) s += wsum[w][ttb + k];
        const float inv = __fdividef(1.0f, s + EPS);
        const float2 lo2 = *reinterpret_cast<float2*>(&acc[k][0]);
        const float2 hi2 = *reinterpret_cast<float2*>(&acc[k][1]);
        out4[(xbase + t0 + ttb + k) * 128 + dg] = make_float4(
            lo2.x * inv, lo2.y * inv, hi2.x * inv, hi2.y * inv);
    }
}

extern "C" void kernel_launch(void* const* d_in, const int* in_sizes, int n_in,
                              void* d_out, int out_size) {
    const float* x  = (const float*)d_in[0];
    const float* Wt = (const float*)d_in[1];
    const float* Wx = (const float*)d_in[2];
    const float* bh = (const float*)d_in[3];
    const float* Wa = (const float*)d_in[4];
    const float* ba = (const float*)d_in[5];
    float* out = (float*)d_out;

    float* gq;
    float* gk;
    cudaGetSymbolAddress((void**)&gq, g_q);
    cudaGetSymbolAddress((void**)&gk, g_k);

    qk_kernel<<<(B * T) / 16, 512>>>((const float4*)x,
                                     (const ulonglong2*)Wt,
                                     (const ulonglong2*)Wx,
                                     (const float4*)bh,
                                     (float4*)gq, (float4*)gk);
    attn_kernel<<<(B * T) / TT, 256>>>((const float4*)x,
                                       (const float4*)gq, (const float4*)gk,
                                       Wa, ba, (float4*)out);
}